// round 14
// baseline (speedup 1.0000x reference)
#include <cuda_runtime.h>
#include <math.h>

#define B_    32
#define T_IN  1024
#define CIN   128
#define F_    256
#define TC    510
#define H_    512
#define G4    2048
#define M_    (TC*B_)
#define NC3   256
#define TCH   64
#define NCH   8

__device__ float g_wt[5*CIN*F_];
__device__ float g_y[(size_t)M_*F_];
__device__ float g_xp[(size_t)TC*G4*B_];
__device__ float g_h[2][B_*H_];
__device__ float g_c[H_*B_];             // [unit][b]
__device__ float g_uacc[4][32*32];       // slot b at [phase][b*32]
__device__ float g_ust[NC3][2][32];      // per-CTA redundant (u, ubin)

typedef unsigned long long ull;

__device__ __forceinline__ ull fma2(ull a, ull b, ull c) {
    ull d;
    asm("fma.rn.f32x2 %0, %1, %2, %3;" : "=l"(d) : "l"(a), "l"(b), "l"(c));
    return d;
}
__device__ __forceinline__ ull add2(ull a, ull b) {
    ull d;
    asm("add.rn.f32x2 %0, %1, %2;" : "=l"(d) : "l"(a), "l"(b));
    return d;
}
__device__ __forceinline__ ull pack2(float lo, float hi) {
    ull d;
    asm("mov.b64 %0, {%1, %2};" : "=l"(d) : "f"(lo), "f"(hi));
    return d;
}
__device__ __forceinline__ float2 unpack2(ull v) {
    float2 r;
    asm("mov.b64 {%0, %1}, %2;" : "=f"(r.x), "=f"(r.y) : "l"(v));
    return r;
}

__global__ void k0_wt(const float* __restrict__ cw) {
    int k = blockIdx.x, f = threadIdx.x;
    g_wt[(size_t)k*F_ + f] = cw[((size_t)f*CIN + (k & 127))*5 + (k >> 7)];
    if (blockIdx.x == 0 && threadIdx.x < 128)
        g_uacc[threadIdx.x >> 5][(threadIdx.x & 31)*32] = 0.f;
}

__global__ __launch_bounds__(256) void k1_conv(
    const float* __restrict__ x, const float* __restrict__ cb,
    const float* __restrict__ gamma, const float* __restrict__ beta,
    const float* __restrict__ mean, const float* __restrict__ var,
    int by0)
{
    __shared__ float As[16][132];
    __shared__ float Bs[16][132];
    const int n0 = blockIdx.x * 128, m0 = (blockIdx.y + by0) * 128;
    const int tid = threadIdx.x, tx = tid & 15, ty = tid >> 4;
    ull acc2[8][4];
#pragma unroll
    for (int i = 0; i < 8; i++)
#pragma unroll
        for (int j = 0; j < 4; j++) acc2[i][j] = 0ULL;

    for (int ks = 0; ks < 40; ks++) {
        const int k0 = ks * 16;
#pragma unroll
        for (int i = 0; i < 2; i++) {
            int idx = tid + i*256, ml = idx >> 2, kc = (idx & 3)*4;
            int m = m0 + ml;
            float4 v = make_float4(0.f,0.f,0.f,0.f);
            if (m < M_) {
                int t = m >> 5, b = m & 31, k = k0 + kc;
                v = *(const float4*)(x + ((size_t)b*T_IN + (size_t)(2*t + (k>>7)))*CIN + (k&127));
            }
            As[kc][ml]=v.x; As[kc+1][ml]=v.y; As[kc+2][ml]=v.z; As[kc+3][ml]=v.w;
        }
#pragma unroll
        for (int i = 0; i < 2; i++) {
            int idx = tid + i*256, kr = idx >> 5, nc = (idx & 31)*4;
            float4 v = *(const float4*)(g_wt + (size_t)(k0+kr)*F_ + n0 + nc);
            Bs[kr][nc]=v.x; Bs[kr][nc+1]=v.y; Bs[kr][nc+2]=v.z; Bs[kr][nc+3]=v.w;
        }
        __syncthreads();
#pragma unroll
        for (int kk = 0; kk < 16; kk++) {
            float a[8];
            *(float4*)&a[0] = *(const float4*)&As[kk][ty*8];
            *(float4*)&a[4] = *(const float4*)&As[kk][ty*8+4];
            ulonglong2 bL = *(const ulonglong2*)&Bs[kk][tx*8];
            ulonglong2 bH = *(const ulonglong2*)&Bs[kk][tx*8+4];
#pragma unroll
            for (int i = 0; i < 8; i++) {
                ull ai = pack2(a[i], a[i]);
                acc2[i][0] = fma2(ai, bL.x, acc2[i][0]);
                acc2[i][1] = fma2(ai, bL.y, acc2[i][1]);
                acc2[i][2] = fma2(ai, bH.x, acc2[i][2]);
                acc2[i][3] = fma2(ai, bH.y, acc2[i][3]);
            }
        }
        __syncthreads();
    }
    const int f0 = n0 + tx*8;
    float invs[8], adds[8], cbs[8];
#pragma unroll
    for (int j = 0; j < 8; j++) {
        float iv = gamma[f0+j] * rsqrtf(var[f0+j] + 1e-5f);
        invs[j] = iv; adds[j] = beta[f0+j] - mean[f0+j]*iv; cbs[j] = cb[f0+j];
    }
#pragma unroll
    for (int i = 0; i < 8; i++) {
        int m = m0 + ty*8 + i;
        if (m < M_) {
            float o[8];
#pragma unroll
            for (int j2 = 0; j2 < 4; j2++) {
                float2 p = unpack2(acc2[i][j2]);
                o[j2*2]   = fmaxf(p.x + cbs[j2*2],   0.f)*invs[j2*2]   + adds[j2*2];
                o[j2*2+1] = fmaxf(p.y + cbs[j2*2+1], 0.f)*invs[j2*2+1] + adds[j2*2+1];
            }
            *(float4*)(g_y + (size_t)m*F_ + f0)   = make_float4(o[0],o[1],o[2],o[3]);
            *(float4*)(g_y + (size_t)m*F_ + f0+4) = make_float4(o[4],o[5],o[6],o[7]);
        }
    }
}

__global__ __launch_bounds__(256) void k2_xproj(
    const float* __restrict__ w_ih, const float* __restrict__ b_ih,
    const float* __restrict__ b_hh, int t0)
{
    extern __shared__ float sm2[];
    float* Ys = sm2;            // 32 x 257
    float* Ws = sm2 + 32*257;   // 32 x 128
    const int t = blockIdx.y + t0, g0 = blockIdx.x * 128;
    const int tid = threadIdx.x, tx = tid & 15, ty = tid >> 4;

    const float* src = g_y + (size_t)t*32*F_;
#pragma unroll
    for (int q = 0; q < 8; q++) {
        int idx = tid + q*256, b = idx >> 6, f4 = idx & 63;
        float4 v = *(const float4*)(src + (size_t)b*F_ + f4*4);
        float* d = Ys + b*257 + f4*4;
        d[0]=v.x; d[1]=v.y; d[2]=v.z; d[3]=v.w;
    }
    ull acc2[4][2];
#pragma unroll
    for (int j = 0; j < 4; j++) { acc2[j][0]=0ULL; acc2[j][1]=0ULL; }

    for (int fs = 0; fs < 8; fs++) {
        __syncthreads();
#pragma unroll
        for (int q = 0; q < 4; q++) {
            int idx = tid + q*256, g = idx >> 3, f4 = idx & 7;
            float4 v = *(const float4*)(w_ih + (size_t)(g0+g)*F_ + fs*32 + f4*4);
            Ws[(f4*4  )*128+g]=v.x; Ws[(f4*4+1)*128+g]=v.y;
            Ws[(f4*4+2)*128+g]=v.z; Ws[(f4*4+3)*128+g]=v.w;
        }
        __syncthreads();
#pragma unroll
        for (int fr = 0; fr < 32; fr++) {
            ulonglong2 aL = *(const ulonglong2*)(Ws + fr*128 + ty*8);
            ulonglong2 aH = *(const ulonglong2*)(Ws + fr*128 + ty*8 + 4);
            float y0 = Ys[(tx*2  )*257 + fs*32 + fr];
            float y1 = Ys[(tx*2+1)*257 + fs*32 + fr];
            ull y00 = pack2(y0, y0);
            ull y11 = pack2(y1, y1);
            acc2[0][0] = fma2(aL.x, y00, acc2[0][0]);
            acc2[1][0] = fma2(aL.y, y00, acc2[1][0]);
            acc2[2][0] = fma2(aH.x, y00, acc2[2][0]);
            acc2[3][0] = fma2(aH.y, y00, acc2[3][0]);
            acc2[0][1] = fma2(aL.x, y11, acc2[0][1]);
            acc2[1][1] = fma2(aL.y, y11, acc2[1][1]);
            acc2[2][1] = fma2(aH.x, y11, acc2[2][1]);
            acc2[3][1] = fma2(aH.y, y11, acc2[3][1]);
        }
    }
#pragma unroll
    for (int j2 = 0; j2 < 4; j2++) {
        int g = g0 + ty*8 + j2*2;
        float bias0 = b_ih[g]   + b_hh[g];
        float bias1 = b_ih[g+1] + b_hh[g+1];
        float2 p0 = unpack2(acc2[j2][0]);
        float2 p1 = unpack2(acc2[j2][1]);
        size_t base0 = ((size_t)t*G4 + g  )*B_ + tx*2;
        size_t base1 = ((size_t)t*G4 + g+1)*B_ + tx*2;
        g_xp[base0]   = p0.x + bias0;
        g_xp[base0+1] = p1.x + bias0;
        g_xp[base1]   = p0.y + bias1;
        g_xp[base1+1] = p1.y + bias1;
    }
}

__device__ __forceinline__ float sigf(float v) { return 1.f/(1.f + __expf(-v)); }

// one LSTM timestep: 256 CTAs x 128 thr (2 units/CTA); PDL
__global__ void __launch_bounds__(128, 2) k3step(
    int t,
    const float* __restrict__ w_hh, const float* __restrict__ w_uh,
    const float* __restrict__ b_uh, float* __restrict__ dout)
{
    extern __shared__ float dsm[];
    float* whh_s = dsm;             // 8 x 512 (16 KB)
    __shared__ float gm[8][33];
    __shared__ float u_s[32], ubin_s[32];
    __shared__ float cpart[2][32];
    __shared__ float wuh_s[2];

    const int cta = blockIdx.x, tid = threadIdx.x;
    const int lane = tid & 31, wid = tid >> 5;
    const int pp = t & 1, pq = pp ^ 1;
    const float* hsrc = g_h[pq];

    cudaTriggerProgrammaticLaunchCompletion();

#pragma unroll
    for (int q = 0; q < 8; q++) {
        int i4 = tid + q*128;
        int r = i4 >> 7, kk = (i4 & 127)*4;
        int grow = (r >> 1)*512 + cta*2 + (r & 1);
        *(float4*)(whh_s + r*512 + kk) = __ldcg((const float4*)(w_hh + (size_t)grow*H_ + kk));
    }
    if (tid < 2) wuh_s[tid] = w_uh[cta*2 + tid];
    const float buh = b_uh[0];

    const int bcol = wid*8 + (lane & 7);
    const int r0 = lane >> 3;
    const int r1 = r0 + 4;
    const int gr0 = (r0 >> 1)*512 + cta*2 + (r0 & 1);
    const int gr1 = (r1 >> 1)*512 + cta*2 + (r1 & 1);

    float xv0 = __ldcg(g_xp + ((size_t)t*G4 + gr0)*B_ + bcol);
    float xv1 = __ldcg(g_xp + ((size_t)t*G4 + gr1)*B_ + bcol);

    cudaGridDependencySynchronize();

    float hp = 0.f, c_in = 0.f;
    if (t > 0 && tid < 64) {
        hp   = __ldcg(hsrc + (tid & 31)*512 + cta*2 + (tid >> 5));
        c_in = __ldcg(g_c + (cta*2 + (tid >> 5))*32 + (tid & 31));
    }

    if (wid == 0) {
        if (t > 0) {
            float up = g_ust[cta][0][lane], ub = g_ust[cta][1][lane];
            float tot = __ldcg(&g_uacc[t & 3][lane*32]);
            float du = sigf(tot + buh);
            float un = ub*du + (1.f-ub)*(up + fminf(du, 1.f - up));
            float ubn = rintf(un);
            u_s[lane] = un; ubin_s[lane] = ubn;
            g_ust[cta][0][lane] = un; g_ust[cta][1][lane] = ubn;
        } else {
            u_s[lane] = 1.f; ubin_s[lane] = 1.f;
            g_ust[cta][0][lane] = 1.f; g_ust[cta][1][lane] = 1.f;
        }
    }
    if (cta == 0 && wid == 1) g_uacc[(t + 2) & 3][lane*32] = 0.f;
    __syncthreads();

    ull acc[64];
#pragma unroll
    for (int j = 0; j < 64; j++) acc[j] = 0ULL;
    if (t > 0) {
#pragma unroll
        for (int i = 0; i < 4; i++) {
            const int kk = 4*lane + 128*i;
            ulonglong2 hv[8];
#pragma unroll
            for (int bl = 0; bl < 8; bl++)
                hv[bl] = __ldcg((const ulonglong2*)(hsrc + (wid*8 + bl)*512 + kk));
#pragma unroll
            for (int g = 0; g < 8; g++) {
                ulonglong2 wv = *(const ulonglong2*)(whh_s + g*512 + kk);
#pragma unroll
                for (int bl = 0; bl < 8; bl++) {
                    acc[g*8+bl] = fma2(wv.x, hv[bl].x, acc[g*8+bl]);
                    acc[g*8+bl] = fma2(wv.y, hv[bl].y, acc[g*8+bl]);
                }
            }
        }
    }
#pragma unroll
    for (int half = 0; half < 2; half++) {
        ull* v = acc + half*32;
#pragma unroll
        for (int s = 16; s > 0; s >>= 1) {
#pragma unroll
            for (int j = 0; j < 16; j++) {
                if (j < s) {
                    bool up_ = (lane & s) != 0;
                    ull keep = up_ ? v[j + s] : v[j];
                    ull send = up_ ? v[j]     : v[j + s];
                    ull rec = __shfl_xor_sync(0xffffffffu, send, s);
                    v[j] = add2(keep, rec);
                }
            }
        }
    }
    {
        float2 p0 = unpack2(acc[0]);
        float2 p1 = unpack2(acc[32]);
        gm[r0][bcol] = p0.x + p0.y + xv0;
        gm[r1][bcol] = p1.x + p1.y + xv1;
    }
    __syncthreads();

    if (tid < 64) {
        int jj = tid >> 5, b = tid & 31;
        float ig = gm[jj][b], fg = gm[2+jj][b], gg = gm[4+jj][b], og = gm[6+jj][b];
        float c = c_in;
        float ct = sigf(fg)*c + sigf(ig)*tanhf(gg);
        float ht = sigf(og)*tanhf(ct);
        float ub = ubin_s[b];
        float cn = ub*ct + (1.f-ub)*c;
        float hn = ub*ht + (1.f-ub)*hp;
        g_h[pp][b*512 + cta*2 + jj] = hn;
        g_c[(cta*2 + jj)*32 + b] = cn;
        if (t == TC-1) dout[(size_t)b*H_ + cta*2 + jj] = hn;
        cpart[jj][b] = cn * wuh_s[jj];
    }
    __syncthreads();
    if (tid < 32) {
        float pd = cpart[0][tid] + cpart[1][tid];
        atomicAdd(&g_uacc[(t + 1) & 3][tid*32], pd);
    }
}

extern "C" void kernel_launch(void* const* d_in, const int* in_sizes, int n_in,
                              void* d_out, int out_size) {
    const float* x     = (const float*)d_in[0];
    const float* cw    = (const float*)d_in[1];
    const float* cb    = (const float*)d_in[2];
    const float* gamma = (const float*)d_in[3];
    const float* beta  = (const float*)d_in[4];
    const float* mean  = (const float*)d_in[5];
    const float* var   = (const float*)d_in[6];
    const float* w_ih  = (const float*)d_in[7];
    const float* w_hh  = (const float*)d_in[8];
    const float* b_ih  = (const float*)d_in[9];
    const float* b_hh  = (const float*)d_in[10];
    const float* w_uh  = (const float*)d_in[11];
    const float* b_uh  = (const float*)d_in[12];
    float* dout = (float*)d_out;

    cudaFuncSetAttribute(k2_xproj, cudaFuncAttributeMaxDynamicSharedMemorySize, 49280);

    cudaStream_t s2;
    cudaStreamCreateWithFlags(&s2, cudaStreamNonBlocking);
    cudaEvent_t evf, ev[NCH];
    cudaEventCreateWithFlags(&evf, cudaEventDisableTiming);
    for (int i = 0; i < NCH; i++)
        cudaEventCreateWithFlags(&ev[i], cudaEventDisableTiming);

    // stream 0: weight prep; fork s2 off it
    k0_wt<<<640, 256>>>(cw);
    cudaEventRecord(evf, 0);
    cudaStreamWaitEvent(s2, evf, 0);

    // s2: chunked conv + x_proj, one event per 64-step chunk
    for (int c = 0; c < NCH; c++) {
        int t0 = c * TCH;
        int tc = (TC - t0 < TCH) ? (TC - t0) : TCH;
        k1_conv<<<dim3(2, 16), 256, 0, s2>>>(x, cb, gamma, beta, mean, var, c*16);
        k2_xproj<<<dim3(16, tc), 256, 49280, s2>>>(w_ih, b_ih, b_hh, t0);
        cudaEventRecord(ev[c], s2);
    }

    // stream 0: PDL-chained steps, gated per chunk
    cudaLaunchAttribute at[1];
    at[0].id = cudaLaunchAttributeProgrammaticStreamSerialization;
    at[0].val.programmaticStreamSerializationAllowed = 1;
    cudaLaunchConfig_t cfg = {};
    cfg.gridDim = dim3(NC3, 1, 1);
    cfg.blockDim = dim3(128, 1, 1);
    cfg.dynamicSmemBytes = 16384;
    cfg.stream = 0;
    cfg.attrs = at;
    cfg.numAttrs = 1;
    for (int t = 0; t < TC; ++t) {
        if ((t & (TCH-1)) == 0)
            cudaStreamWaitEvent(0, ev[t / TCH], 0);
        cudaLaunchKernelEx(&cfg, k3step, t, w_hh, w_uh, b_uh, dout);
    }

    cudaStreamDestroy(s2);
    cudaEventDestroy(evf);
    for (int i = 0; i < NCH; i++) cudaEventDestroy(ev[i]);
}

// round 15
// speedup vs baseline: 1.0297x; 1.0297x over previous
#include <cuda_runtime.h>
#include <math.h>

#define B_    32
#define T_IN  1024
#define CIN   128
#define F_    256
#define TC    510
#define H_    512
#define G4    2048
#define M_    (TC*B_)
#define NC3   256
#define TCH   64
#define NCH   8

__device__ float g_wt[5*CIN*F_];
__device__ float g_y[(size_t)M_*F_];
__device__ float g_xp[(size_t)TC*G4*B_];
__device__ float g_h[2][B_*H_];
__device__ float g_c[H_*B_];             // [unit][b]
__device__ float g_uacc[4][32*32];       // slot b at [phase][b*32]
__device__ float g_ust[NC3][2][32];      // per-CTA redundant (u, ubin)

typedef unsigned long long ull;

__device__ __forceinline__ ull fma2(ull a, ull b, ull c) {
    ull d;
    asm("fma.rn.f32x2 %0, %1, %2, %3;" : "=l"(d) : "l"(a), "l"(b), "l"(c));
    return d;
}
__device__ __forceinline__ ull add2(ull a, ull b) {
    ull d;
    asm("add.rn.f32x2 %0, %1, %2;" : "=l"(d) : "l"(a), "l"(b));
    return d;
}
__device__ __forceinline__ ull pack2(float lo, float hi) {
    ull d;
    asm("mov.b64 %0, {%1, %2};" : "=l"(d) : "f"(lo), "f"(hi));
    return d;
}
__device__ __forceinline__ float2 unpack2(ull v) {
    float2 r;
    asm("mov.b64 {%0, %1}, %2;" : "=f"(r.x), "=f"(r.y) : "l"(v));
    return r;
}

__global__ void k0_wt(const float* __restrict__ cw) {
    int k = blockIdx.x, f = threadIdx.x;
    g_wt[(size_t)k*F_ + f] = cw[((size_t)f*CIN + (k & 127))*5 + (k >> 7)];
    if (blockIdx.x == 0 && threadIdx.x < 128)
        g_uacc[threadIdx.x >> 5][(threadIdx.x & 31)*32] = 0.f;
}

__global__ __launch_bounds__(256) void k1_conv(
    const float* __restrict__ x, const float* __restrict__ cb,
    const float* __restrict__ gamma, const float* __restrict__ beta,
    const float* __restrict__ mean, const float* __restrict__ var)
{
    __shared__ float As[16][132];
    __shared__ float Bs[16][132];
    const int n0 = blockIdx.x * 128, m0 = blockIdx.y * 128;
    const int tid = threadIdx.x, tx = tid & 15, ty = tid >> 4;
    ull acc2[8][4];
#pragma unroll
    for (int i = 0; i < 8; i++)
#pragma unroll
        for (int j = 0; j < 4; j++) acc2[i][j] = 0ULL;

    for (int ks = 0; ks < 40; ks++) {
        const int k0 = ks * 16;
#pragma unroll
        for (int i = 0; i < 2; i++) {
            int idx = tid + i*256, ml = idx >> 2, kc = (idx & 3)*4;
            int m = m0 + ml;
            float4 v = make_float4(0.f,0.f,0.f,0.f);
            if (m < M_) {
                int t = m >> 5, b = m & 31, k = k0 + kc;
                v = *(const float4*)(x + ((size_t)b*T_IN + (size_t)(2*t + (k>>7)))*CIN + (k&127));
            }
            As[kc][ml]=v.x; As[kc+1][ml]=v.y; As[kc+2][ml]=v.z; As[kc+3][ml]=v.w;
        }
#pragma unroll
        for (int i = 0; i < 2; i++) {
            int idx = tid + i*256, kr = idx >> 5, nc = (idx & 31)*4;
            float4 v = *(const float4*)(g_wt + (size_t)(k0+kr)*F_ + n0 + nc);
            Bs[kr][nc]=v.x; Bs[kr][nc+1]=v.y; Bs[kr][nc+2]=v.z; Bs[kr][nc+3]=v.w;
        }
        __syncthreads();
#pragma unroll
        for (int kk = 0; kk < 16; kk++) {
            float a[8];
            *(float4*)&a[0] = *(const float4*)&As[kk][ty*8];
            *(float4*)&a[4] = *(const float4*)&As[kk][ty*8+4];
            ulonglong2 bL = *(const ulonglong2*)&Bs[kk][tx*8];
            ulonglong2 bH = *(const ulonglong2*)&Bs[kk][tx*8+4];
#pragma unroll
            for (int i = 0; i < 8; i++) {
                ull ai = pack2(a[i], a[i]);
                acc2[i][0] = fma2(ai, bL.x, acc2[i][0]);
                acc2[i][1] = fma2(ai, bL.y, acc2[i][1]);
                acc2[i][2] = fma2(ai, bH.x, acc2[i][2]);
                acc2[i][3] = fma2(ai, bH.y, acc2[i][3]);
            }
        }
        __syncthreads();
    }
    const int f0 = n0 + tx*8;
    float invs[8], adds[8], cbs[8];
#pragma unroll
    for (int j = 0; j < 8; j++) {
        float iv = gamma[f0+j] * rsqrtf(var[f0+j] + 1e-5f);
        invs[j] = iv; adds[j] = beta[f0+j] - mean[f0+j]*iv; cbs[j] = cb[f0+j];
    }
#pragma unroll
    for (int i = 0; i < 8; i++) {
        int m = m0 + ty*8 + i;
        if (m < M_) {
            float o[8];
#pragma unroll
            for (int j2 = 0; j2 < 4; j2++) {
                float2 p = unpack2(acc2[i][j2]);
                o[j2*2]   = fmaxf(p.x + cbs[j2*2],   0.f)*invs[j2*2]   + adds[j2*2];
                o[j2*2+1] = fmaxf(p.y + cbs[j2*2+1], 0.f)*invs[j2*2+1] + adds[j2*2+1];
            }
            *(float4*)(g_y + (size_t)m*F_ + f0)   = make_float4(o[0],o[1],o[2],o[3]);
            *(float4*)(g_y + (size_t)m*F_ + f0+4) = make_float4(o[4],o[5],o[6],o[7]);
        }
    }
}

__global__ __launch_bounds__(256) void k2_xproj(
    const float* __restrict__ w_ih, const float* __restrict__ b_ih,
    const float* __restrict__ b_hh, int t0)
{
    extern __shared__ float sm2[];
    float* Ys = sm2;            // 32 x 257
    float* Ws = sm2 + 32*257;   // 32 x 128
    const int t = blockIdx.y + t0, g0 = blockIdx.x * 128;
    const int tid = threadIdx.x, tx = tid & 15, ty = tid >> 4;

    const float* src = g_y + (size_t)t*32*F_;
#pragma unroll
    for (int q = 0; q < 8; q++) {
        int idx = tid + q*256, b = idx >> 6, f4 = idx & 63;
        float4 v = *(const float4*)(src + (size_t)b*F_ + f4*4);
        float* d = Ys + b*257 + f4*4;
        d[0]=v.x; d[1]=v.y; d[2]=v.z; d[3]=v.w;
    }
    ull acc2[4][2];
#pragma unroll
    for (int j = 0; j < 4; j++) { acc2[j][0]=0ULL; acc2[j][1]=0ULL; }

    for (int fs = 0; fs < 8; fs++) {
        __syncthreads();
#pragma unroll
        for (int q = 0; q < 4; q++) {
            int idx = tid + q*256, g = idx >> 3, f4 = idx & 7;
            float4 v = *(const float4*)(w_ih + (size_t)(g0+g)*F_ + fs*32 + f4*4);
            Ws[(f4*4  )*128+g]=v.x; Ws[(f4*4+1)*128+g]=v.y;
            Ws[(f4*4+2)*128+g]=v.z; Ws[(f4*4+3)*128+g]=v.w;
        }
        __syncthreads();
#pragma unroll
        for (int fr = 0; fr < 32; fr++) {
            ulonglong2 aL = *(const ulonglong2*)(Ws + fr*128 + ty*8);
            ulonglong2 aH = *(const ulonglong2*)(Ws + fr*128 + ty*8 + 4);
            float y0 = Ys[(tx*2  )*257 + fs*32 + fr];
            float y1 = Ys[(tx*2+1)*257 + fs*32 + fr];
            ull y00 = pack2(y0, y0);
            ull y11 = pack2(y1, y1);
            acc2[0][0] = fma2(aL.x, y00, acc2[0][0]);
            acc2[1][0] = fma2(aL.y, y00, acc2[1][0]);
            acc2[2][0] = fma2(aH.x, y00, acc2[2][0]);
            acc2[3][0] = fma2(aH.y, y00, acc2[3][0]);
            acc2[0][1] = fma2(aL.x, y11, acc2[0][1]);
            acc2[1][1] = fma2(aL.y, y11, acc2[1][1]);
            acc2[2][1] = fma2(aH.x, y11, acc2[2][1]);
            acc2[3][1] = fma2(aH.y, y11, acc2[3][1]);
        }
    }
#pragma unroll
    for (int j2 = 0; j2 < 4; j2++) {
        int g = g0 + ty*8 + j2*2;
        float bias0 = b_ih[g]   + b_hh[g];
        float bias1 = b_ih[g+1] + b_hh[g+1];
        float2 p0 = unpack2(acc2[j2][0]);
        float2 p1 = unpack2(acc2[j2][1]);
        size_t base0 = ((size_t)t*G4 + g  )*B_ + tx*2;
        size_t base1 = ((size_t)t*G4 + g+1)*B_ + tx*2;
        g_xp[base0]   = p0.x + bias0;
        g_xp[base0+1] = p1.x + bias0;
        g_xp[base1]   = p0.y + bias1;
        g_xp[base1+1] = p1.y + bias1;
    }
}

__device__ __forceinline__ float sigf(float v) { return 1.f/(1.f + __expf(-v)); }

// one LSTM timestep: 256 CTAs x 128 thr (2 units/CTA); PDL
__global__ void __launch_bounds__(128, 2) k3step(
    int t,
    const float* __restrict__ w_hh, const float* __restrict__ w_uh,
    const float* __restrict__ b_uh, float* __restrict__ dout)
{
    extern __shared__ float dsm[];
    float* whh_s = dsm;             // 8 x 512 (16 KB)
    __shared__ float gm[8][33];
    __shared__ float u_s[32], ubin_s[32];
    __shared__ float cpart[2][32];
    __shared__ float wuh_s[2];

    const int cta = blockIdx.x, tid = threadIdx.x;
    const int lane = tid & 31, wid = tid >> 5;
    const int pp = t & 1, pq = pp ^ 1;
    const float* hsrc = g_h[pq];

    cudaTriggerProgrammaticLaunchCompletion();

#pragma unroll
    for (int q = 0; q < 8; q++) {
        int i4 = tid + q*128;
        int r = i4 >> 7, kk = (i4 & 127)*4;
        int grow = (r >> 1)*512 + cta*2 + (r & 1);
        *(float4*)(whh_s + r*512 + kk) = __ldcg((const float4*)(w_hh + (size_t)grow*H_ + kk));
    }
    if (tid < 2) wuh_s[tid] = w_uh[cta*2 + tid];
    const float buh = b_uh[0];

    const int bcol = wid*8 + (lane & 7);
    const int r0 = lane >> 3;
    const int r1 = r0 + 4;
    const int gr0 = (r0 >> 1)*512 + cta*2 + (r0 & 1);
    const int gr1 = (r1 >> 1)*512 + cta*2 + (r1 & 1);

    float xv0 = __ldcg(g_xp + ((size_t)t*G4 + gr0)*B_ + bcol);
    float xv1 = __ldcg(g_xp + ((size_t)t*G4 + gr1)*B_ + bcol);

    cudaGridDependencySynchronize();

    float hp = 0.f, c_in = 0.f;
    if (t > 0 && tid < 64) {
        hp   = __ldcg(hsrc + (tid & 31)*512 + cta*2 + (tid >> 5));
        c_in = __ldcg(g_c + (cta*2 + (tid >> 5))*32 + (tid & 31));
    }

    if (wid == 0) {
        if (t > 0) {
            float up = g_ust[cta][0][lane], ub = g_ust[cta][1][lane];
            float tot = __ldcg(&g_uacc[t & 3][lane*32]);
            float du = sigf(tot + buh);
            float un = ub*du + (1.f-ub)*(up + fminf(du, 1.f - up));
            float ubn = rintf(un);
            u_s[lane] = un; ubin_s[lane] = ubn;
            g_ust[cta][0][lane] = un; g_ust[cta][1][lane] = ubn;
        } else {
            u_s[lane] = 1.f; ubin_s[lane] = 1.f;
            g_ust[cta][0][lane] = 1.f; g_ust[cta][1][lane] = 1.f;
        }
    }
    if (cta == 0 && wid == 1) g_uacc[(t + 2) & 3][lane*32] = 0.f;
    __syncthreads();

    ull acc[64];
#pragma unroll
    for (int j = 0; j < 64; j++) acc[j] = 0ULL;
    if (t > 0) {
#pragma unroll
        for (int i = 0; i < 4; i++) {
            const int kk = 4*lane + 128*i;
            ulonglong2 hv[8];
#pragma unroll
            for (int bl = 0; bl < 8; bl++)
                hv[bl] = __ldcg((const ulonglong2*)(hsrc + (wid*8 + bl)*512 + kk));
#pragma unroll
            for (int g = 0; g < 8; g++) {
                ulonglong2 wv = *(const ulonglong2*)(whh_s + g*512 + kk);
#pragma unroll
                for (int bl = 0; bl < 8; bl++) {
                    acc[g*8+bl] = fma2(wv.x, hv[bl].x, acc[g*8+bl]);
                    acc[g*8+bl] = fma2(wv.y, hv[bl].y, acc[g*8+bl]);
                }
            }
        }
    }
#pragma unroll
    for (int half = 0; half < 2; half++) {
        ull* v = acc + half*32;
#pragma unroll
        for (int s = 16; s > 0; s >>= 1) {
#pragma unroll
            for (int j = 0; j < 16; j++) {
                if (j < s) {
                    bool up_ = (lane & s) != 0;
                    ull keep = up_ ? v[j + s] : v[j];
                    ull send = up_ ? v[j]     : v[j + s];
                    ull rec = __shfl_xor_sync(0xffffffffu, send, s);
                    v[j] = add2(keep, rec);
                }
            }
        }
    }
    {
        float2 p0 = unpack2(acc[0]);
        float2 p1 = unpack2(acc[32]);
        gm[r0][bcol] = p0.x + p0.y + xv0;
        gm[r1][bcol] = p1.x + p1.y + xv1;
    }
    __syncthreads();

    if (tid < 64) {
        int jj = tid >> 5, b = tid & 31;
        float ig = gm[jj][b], fg = gm[2+jj][b], gg = gm[4+jj][b], og = gm[6+jj][b];
        float c = c_in;
        float ct = sigf(fg)*c + sigf(ig)*tanhf(gg);
        float ht = sigf(og)*tanhf(ct);
        float ub = ubin_s[b];
        float cn = ub*ct + (1.f-ub)*c;
        float hn = ub*ht + (1.f-ub)*hp;
        g_h[pp][b*512 + cta*2 + jj] = hn;
        g_c[(cta*2 + jj)*32 + b] = cn;
        if (t == TC-1) dout[(size_t)b*H_ + cta*2 + jj] = hn;
        cpart[jj][b] = cn * wuh_s[jj];
    }
    __syncthreads();
    if (tid < 32) {
        float pd = cpart[0][tid] + cpart[1][tid];
        atomicAdd(&g_uacc[(t + 1) & 3][tid*32], pd);
    }
}

extern "C" void kernel_launch(void* const* d_in, const int* in_sizes, int n_in,
                              void* d_out, int out_size) {
    const float* x     = (const float*)d_in[0];
    const float* cw    = (const float*)d_in[1];
    const float* cb    = (const float*)d_in[2];
    const float* gamma = (const float*)d_in[3];
    const float* beta  = (const float*)d_in[4];
    const float* mean  = (const float*)d_in[5];
    const float* var   = (const float*)d_in[6];
    const float* w_ih  = (const float*)d_in[7];
    const float* w_hh  = (const float*)d_in[8];
    const float* b_ih  = (const float*)d_in[9];
    const float* b_hh  = (const float*)d_in[10];
    const float* w_uh  = (const float*)d_in[11];
    const float* b_uh  = (const float*)d_in[12];
    float* dout = (float*)d_out;

    cudaFuncSetAttribute(k2_xproj, cudaFuncAttributeMaxDynamicSharedMemorySize, 49280);

    int prLo, prHi;
    cudaDeviceGetStreamPriorityRange(&prLo, &prHi);   // prLo = lowest priority
    cudaStream_t s2;
    cudaStreamCreateWithPriority(&s2, cudaStreamNonBlocking, prLo);
    cudaEvent_t evf, ev[NCH];
    cudaEventCreateWithFlags(&evf, cudaEventDisableTiming);
    for (int i = 0; i < NCH; i++)
        cudaEventCreateWithFlags(&ev[i], cudaEventDisableTiming);

    // stream 0: weight prep; fork s2 off it
    k0_wt<<<640, 256>>>(cw);
    cudaEventRecord(evf, 0);
    cudaStreamWaitEvent(s2, evf, 0);

    // s2 (low priority): FULL conv, then chunked x_proj with per-chunk events
    k1_conv<<<dim3(2, 128), 256, 0, s2>>>(x, cb, gamma, beta, mean, var);
    for (int c = 0; c < NCH; c++) {
        int t0 = c * TCH;
        int tc = (TC - t0 < TCH) ? (TC - t0) : TCH;
        k2_xproj<<<dim3(16, tc), 256, 49280, s2>>>(w_ih, b_ih, b_hh, t0);
        cudaEventRecord(ev[c], s2);
    }

    // stream 0 (default priority): PDL-chained steps, gated per chunk
    cudaLaunchAttribute at[1];
    at[0].id = cudaLaunchAttributeProgrammaticStreamSerialization;
    at[0].val.programmaticStreamSerializationAllowed = 1;
    cudaLaunchConfig_t cfg = {};
    cfg.gridDim = dim3(NC3, 1, 1);
    cfg.blockDim = dim3(128, 1, 1);
    cfg.dynamicSmemBytes = 16384;
    cfg.stream = 0;
    cfg.attrs = at;
    cfg.numAttrs = 1;
    for (int t = 0; t < TC; ++t) {
        if ((t & (TCH-1)) == 0)
            cudaStreamWaitEvent(0, ev[t / TCH], 0);
        cudaLaunchKernelEx(&cfg, k3step, t, w_hh, w_uh, b_uh, dout);
    }

    cudaStreamDestroy(s2);
    cudaEventDestroy(evf);
    for (int i = 0; i < NCH; i++) cudaEventDestroy(ev[i]);
}

// round 16
// speedup vs baseline: 1.1416x; 1.1087x over previous
#include <cuda_runtime.h>
#include <math.h>

#define B_    32
#define T_IN  1024
#define CIN   128
#define F_    256
#define TC    510
#define H_    512
#define G4    2048
#define M_    (TC*B_)
#define NC3   256

__device__ float g_wt[5*CIN*F_];
__device__ float g_y[(size_t)M_*F_];
__device__ float g_xp[(size_t)TC*G4*B_];
__device__ float g_h[2][B_*H_];
__device__ float g_c[H_*B_];             // [unit][b]
__device__ float g_uacc[4][32*32];       // slot b at [phase][b*32]
__device__ float g_ust[NC3][2][32];      // per-CTA redundant (u, ubin)

typedef unsigned long long ull;

__device__ __forceinline__ ull fma2(ull a, ull b, ull c) {
    ull d;
    asm("fma.rn.f32x2 %0, %1, %2, %3;" : "=l"(d) : "l"(a), "l"(b), "l"(c));
    return d;
}
__device__ __forceinline__ ull add2(ull a, ull b) {
    ull d;
    asm("add.rn.f32x2 %0, %1, %2;" : "=l"(d) : "l"(a), "l"(b));
    return d;
}
__device__ __forceinline__ ull pack2(float lo, float hi) {
    ull d;
    asm("mov.b64 %0, {%1, %2};" : "=l"(d) : "f"(lo), "f"(hi));
    return d;
}
__device__ __forceinline__ float2 unpack2(ull v) {
    float2 r;
    asm("mov.b64 {%0, %1}, %2;" : "=f"(r.x), "=f"(r.y) : "l"(v));
    return r;
}

__global__ void k0_wt(const float* __restrict__ cw) {
    int k = blockIdx.x, f = threadIdx.x;
    g_wt[(size_t)k*F_ + f] = cw[((size_t)f*CIN + (k & 127))*5 + (k >> 7)];
    if (blockIdx.x == 0 && threadIdx.x < 128)
        g_uacc[threadIdx.x >> 5][(threadIdx.x & 31)*32] = 0.f;
}

__global__ __launch_bounds__(256) void k1_conv(
    const float* __restrict__ x, const float* __restrict__ cb,
    const float* __restrict__ gamma, const float* __restrict__ beta,
    const float* __restrict__ mean, const float* __restrict__ var)
{
    __shared__ float As[16][132];
    __shared__ float Bs[16][132];
    const int n0 = blockIdx.x * 128, m0 = blockIdx.y * 128;
    const int tid = threadIdx.x, tx = tid & 15, ty = tid >> 4;
    ull acc2[8][4];
#pragma unroll
    for (int i = 0; i < 8; i++)
#pragma unroll
        for (int j = 0; j < 4; j++) acc2[i][j] = 0ULL;

    for (int ks = 0; ks < 40; ks++) {
        const int k0 = ks * 16;
#pragma unroll
        for (int i = 0; i < 2; i++) {
            int idx = tid + i*256, ml = idx >> 2, kc = (idx & 3)*4;
            int m = m0 + ml;
            float4 v = make_float4(0.f,0.f,0.f,0.f);
            if (m < M_) {
                int t = m >> 5, b = m & 31, k = k0 + kc;
                v = *(const float4*)(x + ((size_t)b*T_IN + (size_t)(2*t + (k>>7)))*CIN + (k&127));
            }
            As[kc][ml]=v.x; As[kc+1][ml]=v.y; As[kc+2][ml]=v.z; As[kc+3][ml]=v.w;
        }
#pragma unroll
        for (int i = 0; i < 2; i++) {
            int idx = tid + i*256, kr = idx >> 5, nc = (idx & 31)*4;
            float4 v = *(const float4*)(g_wt + (size_t)(k0+kr)*F_ + n0 + nc);
            Bs[kr][nc]=v.x; Bs[kr][nc+1]=v.y; Bs[kr][nc+2]=v.z; Bs[kr][nc+3]=v.w;
        }
        __syncthreads();
#pragma unroll
        for (int kk = 0; kk < 16; kk++) {
            float a[8];
            *(float4*)&a[0] = *(const float4*)&As[kk][ty*8];
            *(float4*)&a[4] = *(const float4*)&As[kk][ty*8+4];
            ulonglong2 bL = *(const ulonglong2*)&Bs[kk][tx*8];
            ulonglong2 bH = *(const ulonglong2*)&Bs[kk][tx*8+4];
#pragma unroll
            for (int i = 0; i < 8; i++) {
                ull ai = pack2(a[i], a[i]);
                acc2[i][0] = fma2(ai, bL.x, acc2[i][0]);
                acc2[i][1] = fma2(ai, bL.y, acc2[i][1]);
                acc2[i][2] = fma2(ai, bH.x, acc2[i][2]);
                acc2[i][3] = fma2(ai, bH.y, acc2[i][3]);
            }
        }
        __syncthreads();
    }
    const int f0 = n0 + tx*8;
    float invs[8], adds[8], cbs[8];
#pragma unroll
    for (int j = 0; j < 8; j++) {
        float iv = gamma[f0+j] * rsqrtf(var[f0+j] + 1e-5f);
        invs[j] = iv; adds[j] = beta[f0+j] - mean[f0+j]*iv; cbs[j] = cb[f0+j];
    }
#pragma unroll
    for (int i = 0; i < 8; i++) {
        int m = m0 + ty*8 + i;
        if (m < M_) {
            float o[8];
#pragma unroll
            for (int j2 = 0; j2 < 4; j2++) {
                float2 p = unpack2(acc2[i][j2]);
                o[j2*2]   = fmaxf(p.x + cbs[j2*2],   0.f)*invs[j2*2]   + adds[j2*2];
                o[j2*2+1] = fmaxf(p.y + cbs[j2*2+1], 0.f)*invs[j2*2+1] + adds[j2*2+1];
            }
            *(float4*)(g_y + (size_t)m*F_ + f0)   = make_float4(o[0],o[1],o[2],o[3]);
            *(float4*)(g_y + (size_t)m*F_ + f0+4) = make_float4(o[4],o[5],o[6],o[7]);
        }
    }
}

// K2 v2: 2 timesteps/block, thread tile 8g x 4b, batch-pair f32x2 accumulators.
// smem: Ws [32f][132] (16896B) + Yt [2tz][32f][34] (8704B) = 25600B
__global__ __launch_bounds__(256) void k2_xproj(
    const float* __restrict__ w_ih, const float* __restrict__ b_ih,
    const float* __restrict__ b_hh)
{
    extern __shared__ float sm2[];
    float* Ws = sm2;                 // Ws[f*132 + g]
    float* Yt = sm2 + 32*132;        // Yt[tz*1088 + f*34 + b]
    const int t0 = blockIdx.y * 2, g0 = blockIdx.x * 128;
    const int tid = threadIdx.x;
    const int tz = tid >> 7;         // 0..1 -> timestep t0+tz
    const int tl = tid & 127;
    const int ty = tl >> 3;          // 0..15 gate oct
    const int txb = tl & 7;          // 0..7 batch quad
    const int t = t0 + tz;
    const int ybase = tz*1088 + txb*4;

    ull acc2[8][2];
#pragma unroll
    for (int j = 0; j < 8; j++) { acc2[j][0] = 0ULL; acc2[j][1] = 0ULL; }

    for (int fs = 0; fs < 8; fs++) {
        __syncthreads();
        // stage Ws chunk: 128g x 32f  (lanes over f4: coalesced LDG, 4-way STS)
#pragma unroll
        for (int q = 0; q < 4; q++) {
            int idx = tid + q*256;
            int g = idx >> 3, f4 = idx & 7;
            float4 v = *(const float4*)(w_ih + (size_t)(g0+g)*F_ + fs*32 + f4*4);
            Ws[(f4*4+0)*132 + g] = v.x;
            Ws[(f4*4+1)*132 + g] = v.y;
            Ws[(f4*4+2)*132 + g] = v.z;
            Ws[(f4*4+3)*132 + g] = v.w;
        }
        // stage Yt chunk (transposed): 32b x 32f for this tz
#pragma unroll
        for (int q = 0; q < 2; q++) {
            int idx = tl + q*128;
            int b = idx >> 3, f4 = idx & 7;
            float4 v = *(const float4*)(g_y + ((size_t)t*32 + b)*F_ + fs*32 + f4*4);
            float* d = Yt + tz*1088 + b;
            d[(f4*4+0)*34] = v.x;
            d[(f4*4+1)*34] = v.y;
            d[(f4*4+2)*34] = v.z;
            d[(f4*4+3)*34] = v.w;
        }
        __syncthreads();
#pragma unroll 4
        for (int fr = 0; fr < 32; fr++) {
            float4 wL = *(const float4*)(Ws + fr*132 + ty*8);
            float4 wH = *(const float4*)(Ws + fr*132 + ty*8 + 4);
            ull y01 = *(const ull*)(Yt + ybase + fr*34);
            ull y23 = *(const ull*)(Yt + ybase + fr*34 + 2);
            ull w;
            w = pack2(wL.x, wL.x); acc2[0][0]=fma2(w,y01,acc2[0][0]); acc2[0][1]=fma2(w,y23,acc2[0][1]);
            w = pack2(wL.y, wL.y); acc2[1][0]=fma2(w,y01,acc2[1][0]); acc2[1][1]=fma2(w,y23,acc2[1][1]);
            w = pack2(wL.z, wL.z); acc2[2][0]=fma2(w,y01,acc2[2][0]); acc2[2][1]=fma2(w,y23,acc2[2][1]);
            w = pack2(wL.w, wL.w); acc2[3][0]=fma2(w,y01,acc2[3][0]); acc2[3][1]=fma2(w,y23,acc2[3][1]);
            w = pack2(wH.x, wH.x); acc2[4][0]=fma2(w,y01,acc2[4][0]); acc2[4][1]=fma2(w,y23,acc2[4][1]);
            w = pack2(wH.y, wH.y); acc2[5][0]=fma2(w,y01,acc2[5][0]); acc2[5][1]=fma2(w,y23,acc2[5][1]);
            w = pack2(wH.z, wH.z); acc2[6][0]=fma2(w,y01,acc2[6][0]); acc2[6][1]=fma2(w,y23,acc2[6][1]);
            w = pack2(wH.w, wH.w); acc2[7][0]=fma2(w,y01,acc2[7][0]); acc2[7][1]=fma2(w,y23,acc2[7][1]);
        }
    }
#pragma unroll
    for (int j = 0; j < 8; j++) {
        int g = g0 + ty*8 + j;
        float bias = b_ih[g] + b_hh[g];
        float2 p01 = unpack2(acc2[j][0]);
        float2 p23 = unpack2(acc2[j][1]);
        float4 o = make_float4(p01.x + bias, p01.y + bias, p23.x + bias, p23.y + bias);
        *(float4*)(g_xp + ((size_t)t*G4 + g)*B_ + txb*4) = o;
    }
}

__device__ __forceinline__ float sigf(float v) { return 1.f/(1.f + __expf(-v)); }

// one LSTM timestep: 256 CTAs x 128 thr (2 units/CTA); PDL
__global__ void __launch_bounds__(128, 2) k3step(
    int t,
    const float* __restrict__ w_hh, const float* __restrict__ w_uh,
    const float* __restrict__ b_uh, float* __restrict__ dout)
{
    extern __shared__ float dsm[];
    float* whh_s = dsm;             // 8 x 512 (16 KB)
    __shared__ float gm[8][33];
    __shared__ float u_s[32], ubin_s[32];
    __shared__ float cpart[2][32];
    __shared__ float wuh_s[2];

    const int cta = blockIdx.x, tid = threadIdx.x;
    const int lane = tid & 31, wid = tid >> 5;
    const int pp = t & 1, pq = pp ^ 1;
    const float* hsrc = g_h[pq];

    cudaTriggerProgrammaticLaunchCompletion();

#pragma unroll
    for (int q = 0; q < 8; q++) {
        int i4 = tid + q*128;
        int r = i4 >> 7, kk = (i4 & 127)*4;
        int grow = (r >> 1)*512 + cta*2 + (r & 1);
        *(float4*)(whh_s + r*512 + kk) = __ldcg((const float4*)(w_hh + (size_t)grow*H_ + kk));
    }
    if (tid < 2) wuh_s[tid] = w_uh[cta*2 + tid];
    const float buh = b_uh[0];

    const int bcol = wid*8 + (lane & 7);
    const int r0 = lane >> 3;
    const int r1 = r0 + 4;
    const int gr0 = (r0 >> 1)*512 + cta*2 + (r0 & 1);
    const int gr1 = (r1 >> 1)*512 + cta*2 + (r1 & 1);

    float xv0 = __ldcg(g_xp + ((size_t)t*G4 + gr0)*B_ + bcol);
    float xv1 = __ldcg(g_xp + ((size_t)t*G4 + gr1)*B_ + bcol);

    cudaGridDependencySynchronize();

    float hp = 0.f, c_in = 0.f;
    if (t > 0 && tid < 64) {
        hp   = __ldcg(hsrc + (tid & 31)*512 + cta*2 + (tid >> 5));
        c_in = __ldcg(g_c + (cta*2 + (tid >> 5))*32 + (tid & 31));
    }

    if (wid == 0) {
        if (t > 0) {
            float up = g_ust[cta][0][lane], ub = g_ust[cta][1][lane];
            float tot = __ldcg(&g_uacc[t & 3][lane*32]);
            float du = sigf(tot + buh);
            float un = ub*du + (1.f-ub)*(up + fminf(du, 1.f - up));
            float ubn = rintf(un);
            u_s[lane] = un; ubin_s[lane] = ubn;
            g_ust[cta][0][lane] = un; g_ust[cta][1][lane] = ubn;
        } else {
            u_s[lane] = 1.f; ubin_s[lane] = 1.f;
            g_ust[cta][0][lane] = 1.f; g_ust[cta][1][lane] = 1.f;
        }
    }
    if (cta == 0 && wid == 1) g_uacc[(t + 2) & 3][lane*32] = 0.f;
    __syncthreads();

    ull acc[64];
#pragma unroll
    for (int j = 0; j < 64; j++) acc[j] = 0ULL;
    if (t > 0) {
#pragma unroll
        for (int i = 0; i < 4; i++) {
            const int kk = 4*lane + 128*i;
            ulonglong2 hv[8];
#pragma unroll
            for (int bl = 0; bl < 8; bl++)
                hv[bl] = __ldcg((const ulonglong2*)(hsrc + (wid*8 + bl)*512 + kk));
#pragma unroll
            for (int g = 0; g < 8; g++) {
                ulonglong2 wv = *(const ulonglong2*)(whh_s + g*512 + kk);
#pragma unroll
                for (int bl = 0; bl < 8; bl++) {
                    acc[g*8+bl] = fma2(wv.x, hv[bl].x, acc[g*8+bl]);
                    acc[g*8+bl] = fma2(wv.y, hv[bl].y, acc[g*8+bl]);
                }
            }
        }
    }
#pragma unroll
    for (int half = 0; half < 2; half++) {
        ull* v = acc + half*32;
#pragma unroll
        for (int s = 16; s > 0; s >>= 1) {
#pragma unroll
            for (int j = 0; j < 16; j++) {
                if (j < s) {
                    bool up_ = (lane & s) != 0;
                    ull keep = up_ ? v[j + s] : v[j];
                    ull send = up_ ? v[j]     : v[j + s];
                    ull rec = __shfl_xor_sync(0xffffffffu, send, s);
                    v[j] = add2(keep, rec);
                }
            }
        }
    }
    {
        float2 p0 = unpack2(acc[0]);
        float2 p1 = unpack2(acc[32]);
        gm[r0][bcol] = p0.x + p0.y + xv0;
        gm[r1][bcol] = p1.x + p1.y + xv1;
    }
    __syncthreads();

    if (tid < 64) {
        int jj = tid >> 5, b = tid & 31;
        float ig = gm[jj][b], fg = gm[2+jj][b], gg = gm[4+jj][b], og = gm[6+jj][b];
        float c = c_in;
        float ct = sigf(fg)*c + sigf(ig)*tanhf(gg);
        float ht = sigf(og)*tanhf(ct);
        float ub = ubin_s[b];
        float cn = ub*ct + (1.f-ub)*c;
        float hn = ub*ht + (1.f-ub)*hp;
        g_h[pp][b*512 + cta*2 + jj] = hn;
        g_c[(cta*2 + jj)*32 + b] = cn;
        if (t == TC-1) dout[(size_t)b*H_ + cta*2 + jj] = hn;
        cpart[jj][b] = cn * wuh_s[jj];
    }
    __syncthreads();
    if (tid < 32) {
        float pd = cpart[0][tid] + cpart[1][tid];
        atomicAdd(&g_uacc[(t + 1) & 3][tid*32], pd);
    }
}

extern "C" void kernel_launch(void* const* d_in, const int* in_sizes, int n_in,
                              void* d_out, int out_size) {
    const float* x     = (const float*)d_in[0];
    const float* cw    = (const float*)d_in[1];
    const float* cb    = (const float*)d_in[2];
    const float* gamma = (const float*)d_in[3];
    const float* beta  = (const float*)d_in[4];
    const float* mean  = (const float*)d_in[5];
    const float* var   = (const float*)d_in[6];
    const float* w_ih  = (const float*)d_in[7];
    const float* w_hh  = (const float*)d_in[8];
    const float* b_ih  = (const float*)d_in[9];
    const float* b_hh  = (const float*)d_in[10];
    const float* w_uh  = (const float*)d_in[11];
    const float* b_uh  = (const float*)d_in[12];
    float* dout = (float*)d_out;

    k0_wt<<<640, 256>>>(cw);
    k1_conv<<<dim3(2, 128), 256>>>(x, cb, gamma, beta, mean, var);
    k2_xproj<<<dim3(16, 255), 256, 25600>>>(w_ih, b_ih, b_hh);

    cudaLaunchAttribute at[1];
    at[0].id = cudaLaunchAttributeProgrammaticStreamSerialization;
    at[0].val.programmaticStreamSerializationAllowed = 1;
    cudaLaunchConfig_t cfg = {};
    cfg.gridDim = dim3(NC3, 1, 1);
    cfg.blockDim = dim3(128, 1, 1);
    cfg.dynamicSmemBytes = 16384;
    cfg.stream = 0;
    cfg.attrs = at;
    cfg.numAttrs = 1;
    for (int t = 0; t < TC; ++t)
        cudaLaunchKernelEx(&cfg, k3step, t, w_hh, w_uh, b_uh, dout);
}